// round 6
// baseline (speedup 1.0000x reference)
#include <cuda_runtime.h>
#include <cuda_bf16.h>
#include <cstdint>

// Problem constants
#define BB 4
#define SS 2048
#define DD 512
#define HH 8
#define DK 64
#define DV 64
#define BS (BB * SS)          // 8192 rows total
#define QT2 64                // query rows per attention block
#define NQT2 (SS / QT2)       // 32 q-tiles per batch

// Scratch (device globals: no allocations allowed)
__device__ float g_q[BS * DK];       // pre-scaled by 0.125, tf32-rounded
__device__ float g_k[BS * DK];       // tf32-rounded
__device__ float g_v[BS * DV];       // tf32-rounded
__device__ float g_o[BS * DV];       // tf32-rounded
__device__ float g_woeff[DV * DD];   // 64 x 512, tf32-rounded

// attention dynamic smem layout (floats)
#define KPITCH 68
#define VPITCH 72
#define KBUF   (64 * KPITCH)         // 4352 floats
#define VBUF   (64 * VPITCH)         // 4608 floats
#define SMEM_FLOATS (2 * KBUF + 2 * VBUF)   // 17920 floats = 71680 B

// ---------------------------------------------------------------------------
// helpers
// ---------------------------------------------------------------------------
__device__ __forceinline__ float f2tff(float f) {
    unsigned u;
    asm("cvt.rna.tf32.f32 %0, %1;" : "=r"(u) : "f"(f));
    return __uint_as_float(u);
}
// D(16x8,f32) += A(16x8,tf32,row) * B(8x8,tf32,col)
__device__ __forceinline__ void mma8(float* c, unsigned a0, unsigned a1,
                                     unsigned a2, unsigned a3,
                                     unsigned b0, unsigned b1) {
    asm volatile(
        "mma.sync.aligned.m16n8k8.row.col.f32.tf32.tf32.f32 "
        "{%0,%1,%2,%3}, {%4,%5,%6,%7}, {%8,%9}, {%0,%1,%2,%3};\n"
        : "+f"(c[0]), "+f"(c[1]), "+f"(c[2]), "+f"(c[3])
        : "r"(a0), "r"(a1), "r"(a2), "r"(a3), "r"(b0), "r"(b1));
}
__device__ __forceinline__ void cpa16(uint32_t saddr, const void* gaddr) {
    asm volatile("cp.async.cg.shared.global [%0], [%1], 16;\n"
                 :: "r"(saddr), "l"(gaddr));
}
__device__ __forceinline__ void cpa_commit() {
    asm volatile("cp.async.commit_group;\n");
}
__device__ __forceinline__ void cpa_wait0() {
    asm volatile("cp.async.wait_group 0;\n");
}
__device__ __forceinline__ void cpa_wait1() {
    asm volatile("cp.async.wait_group 1;\n");
}

// ---------------------------------------------------------------------------
// Kernel 1: fold Wo over identical heads (tf32-rounded)
// ---------------------------------------------------------------------------
__global__ void woeff_kernel(const float* __restrict__ Wo) {
    int idx = blockIdx.x * blockDim.x + threadIdx.x;
    if (idx < DV * DD) {
        int r = idx >> 9;
        int c = idx & 511;
        float s = 0.f;
#pragma unroll
        for (int h = 0; h < HH; ++h) s += Wo[((h << 6) + r) * DD + c];
        g_woeff[idx] = f2tff(s);
    }
}

// ---------------------------------------------------------------------------
// Kernel 2: fused projections on tf32 tensor cores (outputs tf32-rounded;
// q pre-scaled by 0.125). 128 threads = 4 warps.
// ---------------------------------------------------------------------------
__global__ void __launch_bounds__(128) proj_mma_kernel(
    const float* __restrict__ query, const float* __restrict__ key,
    const float* __restrict__ Wq, const float* __restrict__ bq,
    const float* __restrict__ Wk, const float* __restrict__ bk,
    const float* __restrict__ Wv, const float* __restrict__ bv)
{
    const int fused = blockIdx.y;           // 0: q, 1: k+v
    const float* A  = fused ? key : query;
    const int m0 = blockIdx.x * 64;

    __shared__ float As[64][36];
    __shared__ float W1s[32][72];
    __shared__ float W2s[32][72];

    const int t    = threadIdx.x;
    const int w    = t >> 5;
    const int lane = t & 31;
    const int g    = lane >> 2;
    const int t4   = lane & 3;

    float c1[8][4] = {};
    float c2[8][4] = {};

    for (int kk = 0; kk < DD; kk += 32) {
        __syncthreads();
#pragma unroll
        for (int u = 0; u < 4; ++u) {
            int fi = t + u * 128;
            int r  = fi >> 3;
            int c4 = (fi & 7) << 2;
            float4 a4 = *(const float4*)(A + (size_t)(m0 + r) * DD + kk + c4);
            As[r][c4 + 0] = f2tff(a4.x);
            As[r][c4 + 1] = f2tff(a4.y);
            As[r][c4 + 2] = f2tff(a4.z);
            As[r][c4 + 3] = f2tff(a4.w);
        }
#pragma unroll
        for (int u = 0; u < 4; ++u) {
            int fi = t + u * 128;
            int r  = fi >> 4;
            int c4 = (fi & 15) << 2;
            const float* Wa = fused ? Wk : Wq;
            float4 w4 = *(const float4*)(Wa + (size_t)(kk + r) * DK + c4);
            W1s[r][c4 + 0] = f2tff(w4.x);
            W1s[r][c4 + 1] = f2tff(w4.y);
            W1s[r][c4 + 2] = f2tff(w4.z);
            W1s[r][c4 + 3] = f2tff(w4.w);
            if (fused) {
                float4 v4 = *(const float4*)(Wv + (size_t)(kk + r) * DK + c4);
                W2s[r][c4 + 0] = f2tff(v4.x);
                W2s[r][c4 + 1] = f2tff(v4.y);
                W2s[r][c4 + 2] = f2tff(v4.z);
                W2s[r][c4 + 3] = f2tff(v4.w);
            }
        }
        __syncthreads();

#pragma unroll
        for (int kt = 0; kt < 4; ++kt) {
            unsigned a0 = __float_as_uint(As[w * 16 + g    ][kt * 8 + t4    ]);
            unsigned a1 = __float_as_uint(As[w * 16 + g + 8][kt * 8 + t4    ]);
            unsigned a2 = __float_as_uint(As[w * 16 + g    ][kt * 8 + t4 + 4]);
            unsigned a3 = __float_as_uint(As[w * 16 + g + 8][kt * 8 + t4 + 4]);
#pragma unroll
            for (int nt = 0; nt < 8; ++nt) {
                unsigned b0 = __float_as_uint(W1s[kt * 8 + t4    ][nt * 8 + g]);
                unsigned b1 = __float_as_uint(W1s[kt * 8 + t4 + 4][nt * 8 + g]);
                mma8(c1[nt], a0, a1, a2, a3, b0, b1);
            }
            if (fused) {
#pragma unroll
                for (int nt = 0; nt < 8; ++nt) {
                    unsigned b0 = __float_as_uint(W2s[kt * 8 + t4    ][nt * 8 + g]);
                    unsigned b1 = __float_as_uint(W2s[kt * 8 + t4 + 4][nt * 8 + g]);
                    mma8(c2[nt], a0, a1, a2, a3, b0, b1);
                }
            }
        }
    }

    const int r0 = m0 + w * 16 + g;
    const float* bias1 = fused ? bk : bq;
    float* out1        = fused ? g_k : g_q;
    const float sc     = fused ? 1.0f : 0.125f;
#pragma unroll
    for (int nt = 0; nt < 8; ++nt) {
        int cc = nt * 8 + 2 * t4;
        float b0 = bias1[cc], b1 = bias1[cc + 1];
        *(float2*)(out1 + (size_t)r0 * DK + cc) =
            make_float2(f2tff((c1[nt][0] + b0) * sc), f2tff((c1[nt][1] + b1) * sc));
        *(float2*)(out1 + (size_t)(r0 + 8) * DK + cc) =
            make_float2(f2tff((c1[nt][2] + b0) * sc), f2tff((c1[nt][3] + b1) * sc));
    }
    if (fused) {
#pragma unroll
        for (int nt = 0; nt < 8; ++nt) {
            int cc = nt * 8 + 2 * t4;
            float b0 = bv[cc], b1 = bv[cc + 1];
            *(float2*)(g_v + (size_t)r0 * DK + cc) =
                make_float2(f2tff(c2[nt][0] + b0), f2tff(c2[nt][1] + b1));
            *(float2*)(g_v + (size_t)(r0 + 8) * DK + cc) =
                make_float2(f2tff(c2[nt][2] + b0), f2tff(c2[nt][3] + b1));
        }
    }
}

// ---------------------------------------------------------------------------
// Kernel 3: causal flash attention, warp-local softmax + shfl P + cp.async
// double-buffered K/V. Block = 64 q-rows, 128 threads = 4 warps.
// warp w owns rows w*16..w*16+15 x ALL 64 keys / 64 dims.
// ---------------------------------------------------------------------------
__global__ void __launch_bounds__(128) attn_kernel() {
    extern __shared__ float smem[];
    float* kbuf[2] = { smem,              smem + KBUF };
    float* vbuf[2] = { smem + 2 * KBUF,   smem + 2 * KBUF + VBUF };

    const int b  = blockIdx.x & 3;
    const int it = (NQT2 - 1) - (blockIdx.x >> 2);   // longest-first

    const int t    = threadIdx.x;
    const int w    = t >> 5;
    const int lane = t & 31;
    const int g    = lane >> 2;
    const int t4   = lane & 3;
    const int r0   = w * 16 + g;          // q-row in tile (and +8)
    const unsigned FULL = 0xffffffffu;

    // ---- stage Q (pre-scaled, pre-rounded) via kbuf0, grab A fragments ----
    const float* qg = g_q + (size_t)(b * SS + it * QT2) * DK;
#pragma unroll
    for (int u = 0; u < 8; ++u) {
        int fi = t + u * 128;          // 1024 float4
        int r  = fi >> 4;
        int c4 = (fi & 15) << 2;
        *(float4*)(kbuf[0] + r * KPITCH + c4) = *(const float4*)(qg + r * DK + c4);
    }
    __syncthreads();
    unsigned aq[8][4];
#pragma unroll
    for (int kt = 0; kt < 8; ++kt) {
        aq[kt][0] = __float_as_uint(kbuf[0][(r0    ) * KPITCH + kt * 8 + t4    ]);
        aq[kt][1] = __float_as_uint(kbuf[0][(r0 + 8) * KPITCH + kt * 8 + t4    ]);
        aq[kt][2] = __float_as_uint(kbuf[0][(r0    ) * KPITCH + kt * 8 + t4 + 4]);
        aq[kt][3] = __float_as_uint(kbuf[0][(r0 + 8) * KPITCH + kt * 8 + t4 + 4]);
    }
    __syncthreads();

    const int ntiles = it + 1;
    const float* kgp = g_k + (size_t)(b * SS) * DK;
    const float* vgp = g_v + (size_t)(b * SS) * DK;
    const int qpos0 = it * QT2 + r0;

    // per-thread copy coordinates (8 float4 per tile per array)
    // fi = t + u*128 ; r = fi>>4 ; c4 = (fi&15)<<2
    // prologue: tile 0 -> buffer 0
    {
        uint32_t kb = (uint32_t)__cvta_generic_to_shared(kbuf[0]);
        uint32_t vb = (uint32_t)__cvta_generic_to_shared(vbuf[0]);
#pragma unroll
        for (int u = 0; u < 8; ++u) {
            int fi = t + u * 128;
            int r  = fi >> 4;
            int c4 = (fi & 15) << 2;
            cpa16(kb + (r * KPITCH + c4) * 4, kgp + (size_t)r * DK + c4);
            cpa16(vb + (r * VPITCH + c4) * 4, vgp + (size_t)r * DK + c4);
        }
        cpa_commit();
    }

    float o[8][4] = {};
    float mrow0 = -1e30f, mrow1 = -1e30f;
    float lrow0 = 0.f,    lrow1 = 0.f;

    const int srcA = (lane & ~3) | (t4 >> 1);
    const int srcB = srcA + 2;
    const bool oddt = (t4 & 1);

    for (int jt = 0; jt < ntiles; ++jt) {
        const int cur = jt & 1;
        if (jt > 0) __syncthreads();   // compute jt-1 fully done (frees buf[(jt+1)&1])
        if (jt + 1 < ntiles) {
            const int nxt = (jt + 1) & 1;
            uint32_t kb = (uint32_t)__cvta_generic_to_shared(kbuf[nxt]);
            uint32_t vb = (uint32_t)__cvta_generic_to_shared(vbuf[nxt]);
            const float* kgn = kgp + (size_t)(jt + 1) * 64 * DK;
            const float* vgn = vgp + (size_t)(jt + 1) * 64 * DK;
#pragma unroll
            for (int u = 0; u < 8; ++u) {
                int fi = t + u * 128;
                int r  = fi >> 4;
                int c4 = (fi & 15) << 2;
                cpa16(kb + (r * KPITCH + c4) * 4, kgn + (size_t)r * DK + c4);
                cpa16(vb + (r * VPITCH + c4) * 4, vgn + (size_t)r * DK + c4);
            }
            cpa_commit();
            cpa_wait1();               // tile jt arrived
        } else {
            cpa_wait0();
        }
        __syncthreads();               // tile jt visible to all warps

        const float* kc = kbuf[cur];
        const float* vc = vbuf[cur];

        // ---- S = Q K^T : warp covers 16 rows x 64 keys ----
        float c[8][4] = {};
#pragma unroll
        for (int kt = 0; kt < 8; ++kt) {
#pragma unroll
            for (int nt = 0; nt < 8; ++nt) {
                unsigned b0 = __float_as_uint(kc[(nt * 8 + g) * KPITCH + kt * 8 + t4    ]);
                unsigned b1 = __float_as_uint(kc[(nt * 8 + g) * KPITCH + kt * 8 + t4 + 4]);
                mma8(c[nt], aq[kt][0], aq[kt][1], aq[kt][2], aq[kt][3], b0, b1);
            }
        }

        // ---- causal mask (diagonal tile only) ----
        if (jt == ntiles - 1) {
#pragma unroll
            for (int nt = 0; nt < 8; ++nt) {
                int kp = jt * 64 + nt * 8 + 2 * t4;
                if (kp     > qpos0)     c[nt][0] = -1e30f;
                if (kp + 1 > qpos0)     c[nt][1] = -1e30f;
                if (kp     > qpos0 + 8) c[nt][2] = -1e30f;
                if (kp + 1 > qpos0 + 8) c[nt][3] = -1e30f;
            }
        }

        // ---- warp-local online softmax (quad reduce) ----
        float rm0 = -1e30f, rm1 = -1e30f;
#pragma unroll
        for (int nt = 0; nt < 8; ++nt) {
            rm0 = fmaxf(rm0, fmaxf(c[nt][0], c[nt][1]));
            rm1 = fmaxf(rm1, fmaxf(c[nt][2], c[nt][3]));
        }
        rm0 = fmaxf(rm0, __shfl_xor_sync(FULL, rm0, 1));
        rm0 = fmaxf(rm0, __shfl_xor_sync(FULL, rm0, 2));
        rm1 = fmaxf(rm1, __shfl_xor_sync(FULL, rm1, 1));
        rm1 = fmaxf(rm1, __shfl_xor_sync(FULL, rm1, 2));

        float nm0 = fmaxf(mrow0, rm0);
        float nm1 = fmaxf(mrow1, rm1);
        float corr0 = __expf(mrow0 - nm0); mrow0 = nm0;
        float corr1 = __expf(mrow1 - nm1); mrow1 = nm1;

        float rs0 = 0.f, rs1 = 0.f;
#pragma unroll
        for (int nt = 0; nt < 8; ++nt) {
            c[nt][0] = f2tff(__expf(c[nt][0] - nm0));
            c[nt][1] = f2tff(__expf(c[nt][1] - nm0));
            c[nt][2] = f2tff(__expf(c[nt][2] - nm1));
            c[nt][3] = f2tff(__expf(c[nt][3] - nm1));
            rs0 += c[nt][0] + c[nt][1];
            rs1 += c[nt][2] + c[nt][3];
        }
        rs0 += __shfl_xor_sync(FULL, rs0, 1);
        rs0 += __shfl_xor_sync(FULL, rs0, 2);
        rs1 += __shfl_xor_sync(FULL, rs1, 1);
        rs1 += __shfl_xor_sync(FULL, rs1, 2);
        lrow0 = lrow0 * corr0 + rs0;
        lrow1 = lrow1 * corr1 + rs1;

#pragma unroll
        for (int nt = 0; nt < 8; ++nt) {
            o[nt][0] *= corr0; o[nt][1] *= corr0;
            o[nt][2] *= corr1; o[nt][3] *= corr1;
        }

        // ---- O += P V : rebuild A-fragments of P by quad shuffles ----
#pragma unroll
        for (int kt = 0; kt < 8; ++kt) {
            float p00 = __shfl_sync(FULL, c[kt][0], srcA);
            float p01 = __shfl_sync(FULL, c[kt][1], srcA);
            float p20 = __shfl_sync(FULL, c[kt][2], srcA);
            float p21 = __shfl_sync(FULL, c[kt][3], srcA);
            float q00 = __shfl_sync(FULL, c[kt][0], srcB);
            float q01 = __shfl_sync(FULL, c[kt][1], srcB);
            float q20 = __shfl_sync(FULL, c[kt][2], srcB);
            float q21 = __shfl_sync(FULL, c[kt][3], srcB);
            unsigned a0 = __float_as_uint(oddt ? p01 : p00);
            unsigned a1 = __float_as_uint(oddt ? p21 : p20);
            unsigned a2 = __float_as_uint(oddt ? q01 : q00);
            unsigned a3 = __float_as_uint(oddt ? q21 : q20);
#pragma unroll
            for (int nt = 0; nt < 8; ++nt) {
                unsigned b0 = __float_as_uint(vc[(kt * 8 + t4    ) * VPITCH + nt * 8 + g]);
                unsigned b1 = __float_as_uint(vc[(kt * 8 + t4 + 4) * VPITCH + nt * 8 + g]);
                mma8(o[nt], a0, a1, a2, a3, b0, b1);
            }
        }
    }

    // ---- epilogue: o = acc / l, tf32-rounded for outgemm ----
    float inv0 = 1.f / lrow0;
    float inv1 = 1.f / lrow1;
    float* og = g_o + (size_t)(b * SS + it * QT2 + w * 16) * DV;
#pragma unroll
    for (int nt = 0; nt < 8; ++nt) {
        int dc = nt * 8 + 2 * t4;
        *(float2*)(og + (size_t)g * DV + dc) =
            make_float2(f2tff(o[nt][0] * inv0), f2tff(o[nt][1] * inv0));
        *(float2*)(og + (size_t)(g + 8) * DV + dc) =
            make_float2(f2tff(o[nt][2] * inv1), f2tff(o[nt][3] * inv1));
    }
}

// ---------------------------------------------------------------------------
// Kernel 4: out[8192,512] = o[8192,64] @ woeff[64,512] + bo  (tf32 mma)
// ---------------------------------------------------------------------------
__global__ void __launch_bounds__(128) outgemm_mma_kernel(
    const float* __restrict__ bo, float* __restrict__ out)
{
    const int m0 = blockIdx.x * 64;
    const int n0 = blockIdx.y * 64;

    __shared__ float Ao[64][68];
    __shared__ float Ws[64][72];

    const int t    = threadIdx.x;
    const int w    = t >> 5;
    const int lane = t & 31;
    const int g    = lane >> 2;
    const int t4   = lane & 3;

#pragma unroll
    for (int u = 0; u < 8; ++u) {
        int fi = t + u * 128;
        int r  = fi >> 4;
        int c4 = (fi & 15) << 2;
        *(float4*)&Ao[r][c4] = *(const float4*)(g_o + (size_t)(m0 + r) * DV + c4);
        *(float4*)&Ws[r][c4] = *(const float4*)(g_woeff + (size_t)r * DD + n0 + c4);
    }
    __syncthreads();

    float c[8][4] = {};
#pragma unroll
    for (int kt = 0; kt < 8; ++kt) {
        unsigned a0 = __float_as_uint(Ao[w * 16 + g    ][kt * 8 + t4    ]);
        unsigned a1 = __float_as_uint(Ao[w * 16 + g + 8][kt * 8 + t4    ]);
        unsigned a2 = __float_as_uint(Ao[w * 16 + g    ][kt * 8 + t4 + 4]);
        unsigned a3 = __float_as_uint(Ao[w * 16 + g + 8][kt * 8 + t4 + 4]);
#pragma unroll
        for (int nt = 0; nt < 8; ++nt) {
            unsigned b0 = __float_as_uint(Ws[kt * 8 + t4    ][nt * 8 + g]);
            unsigned b1 = __float_as_uint(Ws[kt * 8 + t4 + 4][nt * 8 + g]);
            mma8(c[nt], a0, a1, a2, a3, b0, b1);
        }
    }

    const int row0 = m0 + w * 16 + g;
#pragma unroll
    for (int nt = 0; nt < 8; ++nt) {
        int cc = n0 + nt * 8 + 2 * t4;
        float b0 = bo[cc], b1 = bo[cc + 1];
        *(float2*)(out + (size_t)row0 * DD + cc)       = make_float2(c[nt][0] + b0, c[nt][1] + b1);
        *(float2*)(out + (size_t)(row0 + 8) * DD + cc) = make_float2(c[nt][2] + b0, c[nt][3] + b1);
    }
}

// ---------------------------------------------------------------------------
// Launch
// Inputs: 0 query, 1 key, 2 value(unused), 3 Wq, 4 bq, 5 Wk, 6 bk,
//         7 Wv, 8 bv, 9 Wo, 10 bo
// ---------------------------------------------------------------------------
extern "C" void kernel_launch(void* const* d_in, const int* in_sizes, int n_in,
                              void* d_out, int out_size)
{
    const float* query = (const float*)d_in[0];
    const float* key   = (const float*)d_in[1];
    const float* Wq    = (const float*)d_in[3];
    const float* bq    = (const float*)d_in[4];
    const float* Wk    = (const float*)d_in[5];
    const float* bk    = (const float*)d_in[6];
    const float* Wv    = (const float*)d_in[7];
    const float* bv    = (const float*)d_in[8];
    const float* Wo    = (const float*)d_in[9];
    const float* bo    = (const float*)d_in[10];
    float* out = (float*)d_out;

    cudaFuncSetAttribute(attn_kernel,
                         cudaFuncAttributeMaxDynamicSharedMemorySize,
                         SMEM_FLOATS * 4);

    woeff_kernel<<<64, 512>>>(Wo);
    proj_mma_kernel<<<dim3(BS / 64, 2), 128>>>(query, key, Wq, bq, Wk, bk, Wv, bv);
    attn_kernel<<<BB * NQT2, 128, SMEM_FLOATS * 4>>>();
    outgemm_mma_kernel<<<dim3(BS / 64, DD / 64), 128>>>(bo, out);
}

// round 7
// speedup vs baseline: 1.5995x; 1.5995x over previous
#include <cuda_runtime.h>
#include <cuda_fp16.h>
#include <cstdint>

// Problem constants
#define BB 4
#define SS 2048
#define DD 512
#define HH 8
#define DK 64
#define DV 64
#define BS (BB * SS)          // 8192 rows total
#define QT2 64                // query rows per attention block
#define NQT2 (SS / QT2)       // 32 q-tiles per batch

// Scratch (device globals: no allocations allowed)
__device__ unsigned g_q2[BS * DK / 2];   // half2: (q@Wq+bq)*0.125
__device__ unsigned g_k2[BS * DK / 2];   // half2: k
__device__ __half   g_vT[BB * DV * SS];  // half, per-batch transposed [dim][seq]
__device__ float    g_o[BS * DV];        // tf32-rounded
__device__ float    g_woeff[DV * DD];    // 64 x 512, tf32-rounded

// ---------------------------------------------------------------------------
// helpers
// ---------------------------------------------------------------------------
__device__ __forceinline__ float f2tff(float f) {
    unsigned u;
    asm("cvt.rna.tf32.f32 %0, %1;" : "=r"(u) : "f"(f));
    return __uint_as_float(u);
}
// D(16x8,f32) += A(16x8,tf32,row) * B(8x8,tf32,col)
__device__ __forceinline__ void mma8(float* c, unsigned a0, unsigned a1,
                                     unsigned a2, unsigned a3,
                                     unsigned b0, unsigned b1) {
    asm volatile(
        "mma.sync.aligned.m16n8k8.row.col.f32.tf32.tf32.f32 "
        "{%0,%1,%2,%3}, {%4,%5,%6,%7}, {%8,%9}, {%0,%1,%2,%3};\n"
        : "+f"(c[0]), "+f"(c[1]), "+f"(c[2]), "+f"(c[3])
        : "r"(a0), "r"(a1), "r"(a2), "r"(a3), "r"(b0), "r"(b1));
}
// D(16x8,f32) += A(16x16,f16,row) * B(16x8,f16,col)
__device__ __forceinline__ void mma16(float* c, unsigned a0, unsigned a1,
                                      unsigned a2, unsigned a3,
                                      unsigned b0, unsigned b1) {
    asm volatile(
        "mma.sync.aligned.m16n8k16.row.col.f32.f16.f16.f32 "
        "{%0,%1,%2,%3}, {%4,%5,%6,%7}, {%8,%9}, {%0,%1,%2,%3};\n"
        : "+f"(c[0]), "+f"(c[1]), "+f"(c[2]), "+f"(c[3])
        : "r"(a0), "r"(a1), "r"(a2), "r"(a3), "r"(b0), "r"(b1));
}
__device__ __forceinline__ unsigned packh2(float hi, float lo) {
    unsigned d;
    asm("cvt.rn.f16x2.f32 %0, %1, %2;" : "=r"(d) : "f"(hi), "f"(lo));
    return d;
}
__device__ __forceinline__ unsigned ex2h2(unsigned x) {
    unsigned d;
    asm("ex2.approx.f16x2 %0, %1;" : "=r"(d) : "r"(x));
    return d;
}
__device__ __forceinline__ void cpa16(uint32_t saddr, const void* gaddr) {
    asm volatile("cp.async.cg.shared.global [%0], [%1], 16;\n"
                 :: "r"(saddr), "l"(gaddr));
}
__device__ __forceinline__ void cpa_commit() {
    asm volatile("cp.async.commit_group;\n");
}
__device__ __forceinline__ void cpa_wait0() {
    asm volatile("cp.async.wait_group 0;\n");
}
__device__ __forceinline__ void cpa_wait1() {
    asm volatile("cp.async.wait_group 1;\n");
}

// ---------------------------------------------------------------------------
// Kernel 1: fold Wo over identical heads (tf32-rounded)
// ---------------------------------------------------------------------------
__global__ void woeff_kernel(const float* __restrict__ Wo) {
    int idx = blockIdx.x * blockDim.x + threadIdx.x;
    if (idx < DV * DD) {
        int r = idx >> 9;
        int c = idx & 511;
        float s = 0.f;
#pragma unroll
        for (int h = 0; h < HH; ++h) s += Wo[((h << 6) + r) * DD + c];
        g_woeff[idx] = f2tff(s);
    }
}

// ---------------------------------------------------------------------------
// Kernel 2: fused projections on tf32 tensor cores; epilogue emits fp16.
// blockIdx.y: 0 -> q (scaled 0.125); 1 -> k AND vT (shared A tile).
// 128 threads = 4 warps.
// ---------------------------------------------------------------------------
__global__ void __launch_bounds__(128) proj_mma_kernel(
    const float* __restrict__ query, const float* __restrict__ key,
    const float* __restrict__ Wq, const float* __restrict__ bq,
    const float* __restrict__ Wk, const float* __restrict__ bk,
    const float* __restrict__ Wv, const float* __restrict__ bv)
{
    const int fused = blockIdx.y;           // 0: q, 1: k+v
    const float* A  = fused ? key : query;
    const int m0 = blockIdx.x * 64;

    __shared__ float As[64][36];
    __shared__ float W1s[32][72];
    __shared__ float W2s[32][72];

    const int t    = threadIdx.x;
    const int w    = t >> 5;
    const int lane = t & 31;
    const int g    = lane >> 2;
    const int t4   = lane & 3;

    float c1[8][4] = {};
    float c2[8][4] = {};

    for (int kk = 0; kk < DD; kk += 32) {
        __syncthreads();
#pragma unroll
        for (int u = 0; u < 4; ++u) {
            int fi = t + u * 128;
            int r  = fi >> 3;
            int c4 = (fi & 7) << 2;
            float4 a4 = *(const float4*)(A + (size_t)(m0 + r) * DD + kk + c4);
            As[r][c4 + 0] = f2tff(a4.x);
            As[r][c4 + 1] = f2tff(a4.y);
            As[r][c4 + 2] = f2tff(a4.z);
            As[r][c4 + 3] = f2tff(a4.w);
        }
#pragma unroll
        for (int u = 0; u < 4; ++u) {
            int fi = t + u * 128;
            int r  = fi >> 4;
            int c4 = (fi & 15) << 2;
            const float* Wa = fused ? Wk : Wq;
            float4 w4 = *(const float4*)(Wa + (size_t)(kk + r) * DK + c4);
            W1s[r][c4 + 0] = f2tff(w4.x);
            W1s[r][c4 + 1] = f2tff(w4.y);
            W1s[r][c4 + 2] = f2tff(w4.z);
            W1s[r][c4 + 3] = f2tff(w4.w);
            if (fused) {
                float4 v4 = *(const float4*)(Wv + (size_t)(kk + r) * DK + c4);
                W2s[r][c4 + 0] = f2tff(v4.x);
                W2s[r][c4 + 1] = f2tff(v4.y);
                W2s[r][c4 + 2] = f2tff(v4.z);
                W2s[r][c4 + 3] = f2tff(v4.w);
            }
        }
        __syncthreads();

#pragma unroll
        for (int kt = 0; kt < 4; ++kt) {
            unsigned a0 = __float_as_uint(As[w * 16 + g    ][kt * 8 + t4    ]);
            unsigned a1 = __float_as_uint(As[w * 16 + g + 8][kt * 8 + t4    ]);
            unsigned a2 = __float_as_uint(As[w * 16 + g    ][kt * 8 + t4 + 4]);
            unsigned a3 = __float_as_uint(As[w * 16 + g + 8][kt * 8 + t4 + 4]);
#pragma unroll
            for (int nt = 0; nt < 8; ++nt) {
                unsigned b0 = __float_as_uint(W1s[kt * 8 + t4    ][nt * 8 + g]);
                unsigned b1 = __float_as_uint(W1s[kt * 8 + t4 + 4][nt * 8 + g]);
                mma8(c1[nt], a0, a1, a2, a3, b0, b1);
            }
            if (fused) {
#pragma unroll
                for (int nt = 0; nt < 8; ++nt) {
                    unsigned b0 = __float_as_uint(W2s[kt * 8 + t4    ][nt * 8 + g]);
                    unsigned b1 = __float_as_uint(W2s[kt * 8 + t4 + 4][nt * 8 + g]);
                    mma8(c2[nt], a0, a1, a2, a3, b0, b1);
                }
            }
        }
    }

    // epilogue -> fp16
    const int r0 = m0 + w * 16 + g;            // global row
    const float* bias1 = fused ? bk : bq;
    unsigned* out1     = fused ? g_k2 : g_q2;
    const float sc     = fused ? 1.0f : 0.125f;
#pragma unroll
    for (int nt = 0; nt < 8; ++nt) {
        int cc = nt * 8 + 2 * t4;
        float b0 = bias1[cc], b1 = bias1[cc + 1];
        out1[r0 * 32 + (cc >> 1)] =
            packh2((c1[nt][1] + b1) * sc, (c1[nt][0] + b0) * sc);
        out1[(r0 + 8) * 32 + (cc >> 1)] =
            packh2((c1[nt][3] + b1) * sc, (c1[nt][2] + b0) * sc);
    }
    if (fused) {
        const int bq_ = r0 >> 11;              // batch
        const int sq  = r0 & 2047;             // seq within batch
#pragma unroll
        for (int nt = 0; nt < 8; ++nt) {
            int cc = nt * 8 + 2 * t4;
            float b0 = bv[cc], b1 = bv[cc + 1];
            __half* base0 = g_vT + ((size_t)bq_ * 64 + cc) * SS;
            __half* base1 = g_vT + ((size_t)bq_ * 64 + cc + 1) * SS;
            base0[sq]     = __float2half(c2[nt][0] + b0);
            base1[sq]     = __float2half(c2[nt][1] + b1);
            base0[sq + 8] = __float2half(c2[nt][2] + b0);
            base1[sq + 8] = __float2half(c2[nt][3] + b1);
        }
    }
}

// ---------------------------------------------------------------------------
// Kernel 3: causal flash attention, fp16 tensor cores.
// Block = 64 q-rows, 128 threads = 4 warps; warp w: rows w*16..+15 x all keys.
// K tile [key][dim] half (pitch 36 u32); V^T tile [dim][key] half (pitch 36).
// ex2.approx.f16x2 output doubles as PV A-fragments; row sums via ones-MMA.
// ---------------------------------------------------------------------------
#define P32 36
__global__ void __launch_bounds__(128) attn_kernel() {
    __shared__ unsigned kb[2][64 * P32];
    __shared__ unsigned vb[2][64 * P32];

    const int b  = blockIdx.x & 3;
    const int it = (NQT2 - 1) - (blockIdx.x >> 2);   // longest-first

    const int t    = threadIdx.x;
    const int w    = t >> 5;
    const int lane = t & 31;
    const int g    = lane >> 2;
    const int t4   = lane & 3;
    const int r0   = w * 16 + g;
    const unsigned FULL = 0xffffffffu;
    const unsigned ONES2 = 0x3C003C00u;   // half2 {1.0, 1.0}
    const float L2E = 1.44269504f;

    // ---- stage Q tile (64 rows x 32 u32) into kb[0], grab A fragments ----
    const __half* qh = (const __half*)g_q2 + (size_t)(b * SS + it * QT2) * DK;
#pragma unroll
    for (int u = 0; u < 4; ++u) {
        int fi = t + u * 128;         // 512 chunks of 16B
        int r  = fi >> 3;
        int c  = fi & 7;
        *(float4*)&kb[0][r * P32 + c * 4] = *(const float4*)(qh + r * DK + c * 8);
    }
    __syncthreads();
    unsigned aq[4][4];
#pragma unroll
    for (int kt = 0; kt < 4; ++kt) {
        aq[kt][0] = kb[0][(r0    ) * P32 + kt * 8 + t4    ];
        aq[kt][1] = kb[0][(r0 + 8) * P32 + kt * 8 + t4    ];
        aq[kt][2] = kb[0][(r0    ) * P32 + kt * 8 + t4 + 4];
        aq[kt][3] = kb[0][(r0 + 8) * P32 + kt * 8 + t4 + 4];
    }
    __syncthreads();

    const int ntiles = it + 1;
    const __half* kgp = (const __half*)g_k2 + (size_t)(b * SS) * DK;
    const __half* vgp = g_vT + (size_t)b * 64 * SS;
    const int qpos0 = it * QT2 + r0;

    // prologue: tile 0 -> buffer 0 (4 K-chunks + 4 V-chunks per thread)
    {
        uint32_t kba = (uint32_t)__cvta_generic_to_shared(&kb[0][0]);
        uint32_t vba = (uint32_t)__cvta_generic_to_shared(&vb[0][0]);
#pragma unroll
        for (int u = 0; u < 4; ++u) {
            int fi = t + u * 128;
            int r  = fi >> 3;
            int c  = fi & 7;
            cpa16(kba + (r * P32 + c * 4) * 4, kgp + (size_t)r * DK + c * 8);
            cpa16(vba + (r * P32 + c * 4) * 4, vgp + (size_t)r * SS + c * 8);
        }
        cpa_commit();
    }

    float o[8][4] = {};
    float mrow0 = -1e30f, mrow1 = -1e30f;
    float lrow0 = 0.f,    lrow1 = 0.f;

    for (int jt = 0; jt < ntiles; ++jt) {
        const int cur = jt & 1;
        if (jt > 0) __syncthreads();   // frees buf[(jt+1)&1]
        if (jt + 1 < ntiles) {
            const int nxt = (jt + 1) & 1;
            uint32_t kba = (uint32_t)__cvta_generic_to_shared(&kb[nxt][0]);
            uint32_t vba = (uint32_t)__cvta_generic_to_shared(&vb[nxt][0]);
            const __half* kgn = kgp + (size_t)(jt + 1) * 64 * DK;
            const __half* vgn = vgp + (size_t)(jt + 1) * 64;
#pragma unroll
            for (int u = 0; u < 4; ++u) {
                int fi = t + u * 128;
                int r  = fi >> 3;
                int c  = fi & 7;
                cpa16(kba + (r * P32 + c * 4) * 4, kgn + (size_t)r * DK + c * 8);
                cpa16(vba + (r * P32 + c * 4) * 4, vgn + (size_t)r * SS + c * 8);
            }
            cpa_commit();
            cpa_wait1();
        } else {
            cpa_wait0();
        }
        __syncthreads();

        const unsigned* kc = &kb[cur][0];
        const unsigned* vc = &vb[cur][0];

        // ---- S = Q K^T : 4 k-groups x 8 key-groups ----
        float c[8][4] = {};
#pragma unroll
        for (int kt = 0; kt < 4; ++kt) {
#pragma unroll
            for (int nt = 0; nt < 8; ++nt) {
                unsigned b0 = kc[(nt * 8 + g) * P32 + kt * 8 + t4    ];
                unsigned b1 = kc[(nt * 8 + g) * P32 + kt * 8 + t4 + 4];
                mma16(c[nt], aq[kt][0], aq[kt][1], aq[kt][2], aq[kt][3], b0, b1);
            }
        }

        // ---- causal mask (diagonal tile only) ----
        if (jt == ntiles - 1) {
#pragma unroll
            for (int nt = 0; nt < 8; ++nt) {
                int kp = jt * 64 + nt * 8 + 2 * t4;
                if (kp     > qpos0)     c[nt][0] = -1e30f;
                if (kp + 1 > qpos0)     c[nt][1] = -1e30f;
                if (kp     > qpos0 + 8) c[nt][2] = -1e30f;
                if (kp + 1 > qpos0 + 8) c[nt][3] = -1e30f;
            }
        }

        // ---- warp-local online softmax (quad reduce for max) ----
        float rm0 = -1e30f, rm1 = -1e30f;
#pragma unroll
        for (int nt = 0; nt < 8; ++nt) {
            rm0 = fmaxf(rm0, fmaxf(c[nt][0], c[nt][1]));
            rm1 = fmaxf(rm1, fmaxf(c[nt][2], c[nt][3]));
        }
        rm0 = fmaxf(rm0, __shfl_xor_sync(FULL, rm0, 1));
        rm0 = fmaxf(rm0, __shfl_xor_sync(FULL, rm0, 2));
        rm1 = fmaxf(rm1, __shfl_xor_sync(FULL, rm1, 1));
        rm1 = fmaxf(rm1, __shfl_xor_sync(FULL, rm1, 2));

        float nm0 = fmaxf(mrow0, rm0);
        float nm1 = fmaxf(mrow1, rm1);
        float corr0 = __expf(mrow0 - nm0); mrow0 = nm0;
        float corr1 = __expf(mrow1 - nm1); mrow1 = nm1;
        float nl0 = nm0 * L2E;
        float nl1 = nm1 * L2E;

#pragma unroll
        for (int nt = 0; nt < 8; ++nt) {
            o[nt][0] *= corr0; o[nt][1] *= corr0;
            o[nt][2] *= corr1; o[nt][3] *= corr1;
        }

        // ---- exp (f16x2) -> PV A-frags + ones-MMA row sums + PV MMA ----
        float ds[4] = {0.f, 0.f, 0.f, 0.f};
#pragma unroll
        for (int kt = 0; kt < 4; ++kt) {
            int ne = 2 * kt, no_ = 2 * kt + 1;
            unsigned aP0 = ex2h2(packh2(c[ne ][1] * L2E - nl0, c[ne ][0] * L2E - nl0));
            unsigned aP1 = ex2h2(packh2(c[ne ][3] * L2E - nl1, c[ne ][2] * L2E - nl1));
            unsigned aP2 = ex2h2(packh2(c[no_][1] * L2E - nl0, c[no_][0] * L2E - nl0));
            unsigned aP3 = ex2h2(packh2(c[no_][3] * L2E - nl1, c[no_][2] * L2E - nl1));
            mma16(ds, aP0, aP1, aP2, aP3, ONES2, ONES2);
#pragma unroll
            for (int nt = 0; nt < 8; ++nt) {
                unsigned b0 = vc[(nt * 8 + g) * P32 + kt * 8 + t4    ];
                unsigned b1 = vc[(nt * 8 + g) * P32 + kt * 8 + t4 + 4];
                mma16(o[nt], aP0, aP1, aP2, aP3, b0, b1);
            }
        }
        lrow0 = lrow0 * corr0 + ds[0];
        lrow1 = lrow1 * corr1 + ds[2];
    }

    // ---- epilogue: o = acc / l, tf32-rounded for outgemm ----
    float inv0 = 1.f / lrow0;
    float inv1 = 1.f / lrow1;
    float* og = g_o + (size_t)(b * SS + it * QT2 + w * 16) * DV;
#pragma unroll
    for (int nt = 0; nt < 8; ++nt) {
        int dc = nt * 8 + 2 * t4;
        *(float2*)(og + (size_t)g * DV + dc) =
            make_float2(f2tff(o[nt][0] * inv0), f2tff(o[nt][1] * inv0));
        *(float2*)(og + (size_t)(g + 8) * DV + dc) =
            make_float2(f2tff(o[nt][2] * inv1), f2tff(o[nt][3] * inv1));
    }
}

// ---------------------------------------------------------------------------
// Kernel 4: out[8192,512] = o[8192,64] @ woeff[64,512] + bo  (tf32 mma)
// ---------------------------------------------------------------------------
__global__ void __launch_bounds__(128) outgemm_mma_kernel(
    const float* __restrict__ bo, float* __restrict__ out)
{
    const int m0 = blockIdx.x * 64;
    const int n0 = blockIdx.y * 64;

    __shared__ float Ao[64][68];
    __shared__ float Ws[64][72];

    const int t    = threadIdx.x;
    const int w    = t >> 5;
    const int lane = t & 31;
    const int g    = lane >> 2;
    const int t4   = lane & 3;

#pragma unroll
    for (int u = 0; u < 8; ++u) {
        int fi = t + u * 128;
        int r  = fi >> 4;
        int c4 = (fi & 15) << 2;
        *(float4*)&Ao[r][c4] = *(const float4*)(g_o + (size_t)(m0 + r) * DV + c4);
        *(float4*)&Ws[r][c4] = *(const float4*)(g_woeff + (size_t)r * DD + n0 + c4);
    }
    __syncthreads();

    float c[8][4] = {};
#pragma unroll
    for (int kt = 0; kt < 8; ++kt) {
        unsigned a0 = __float_as_uint(Ao[w * 16 + g    ][kt * 8 + t4    ]);
        unsigned a1 = __float_as_uint(Ao[w * 16 + g + 8][kt * 8 + t4    ]);
        unsigned a2 = __float_as_uint(Ao[w * 16 + g    ][kt * 8 + t4 + 4]);
        unsigned a3 = __float_as_uint(Ao[w * 16 + g + 8][kt * 8 + t4 + 4]);
#pragma unroll
        for (int nt = 0; nt < 8; ++nt) {
            unsigned b0 = __float_as_uint(Ws[kt * 8 + t4    ][nt * 8 + g]);
            unsigned b1 = __float_as_uint(Ws[kt * 8 + t4 + 4][nt * 8 + g]);
            mma8(c[nt], a0, a1, a2, a3, b0, b1);
        }
    }

    const int row0 = m0 + w * 16 + g;
#pragma unroll
    for (int nt = 0; nt < 8; ++nt) {
        int cc = n0 + nt * 8 + 2 * t4;
        float b0 = bo[cc], b1 = bo[cc + 1];
        *(float2*)(out + (size_t)row0 * DD + cc)       = make_float2(c[nt][0] + b0, c[nt][1] + b1);
        *(float2*)(out + (size_t)(row0 + 8) * DD + cc) = make_float2(c[nt][2] + b0, c[nt][3] + b1);
    }
}

// ---------------------------------------------------------------------------
// Launch
// Inputs: 0 query, 1 key, 2 value(unused), 3 Wq, 4 bq, 5 Wk, 6 bk,
//         7 Wv, 8 bv, 9 Wo, 10 bo
// ---------------------------------------------------------------------------
extern "C" void kernel_launch(void* const* d_in, const int* in_sizes, int n_in,
                              void* d_out, int out_size)
{
    const float* query = (const float*)d_in[0];
    const float* key   = (const float*)d_in[1];
    const float* Wq    = (const float*)d_in[3];
    const float* bq    = (const float*)d_in[4];
    const float* Wk    = (const float*)d_in[5];
    const float* bk    = (const float*)d_in[6];
    const float* Wv    = (const float*)d_in[7];
    const float* bv    = (const float*)d_in[8];
    const float* Wo    = (const float*)d_in[9];
    const float* bo    = (const float*)d_in[10];
    float* out = (float*)d_out;

    woeff_kernel<<<64, 512>>>(Wo);
    proj_mma_kernel<<<dim3(BS / 64, 2), 128>>>(query, key, Wq, bq, Wk, bk, Wv, bv);
    attn_kernel<<<BB * NQT2, 128>>>();
    outgemm_mma_kernel<<<dim3(BS / 64, DD / 64), 128>>>(bo, out);
}